// round 1
// baseline (speedup 1.0000x reference)
#include <cuda_runtime.h>

#define NSLICE 384
#define NPTS   512
#define TDIM   24
#define FDIM   64
#define ROWSTR (TDIM*FDIM)          // 1536 floats between consecutive n
#define OUT_HALF (16*512*24*64)     // offset of uf in d_out

// scratch (device globals: allocation-free per harness rules)
__device__ float g_G[NPTS * NPTS];              // E @ E^T   (1 MB)
__device__ float g_VW[NSLICE * NPTS * 128];     // [s][n][ xw(64) | uw(64) ]  (~100 MB)

// packed fp32x2 FMA (Blackwell FFMA2): 2 MACs / instruction
__device__ __forceinline__ float2 ffma2(float2 a, float2 b, float2 c) {
    float2 d;
    asm("fma.rn.f32x2 %0, %1, %2, %3;"
        : "=l"(reinterpret_cast<unsigned long long&>(d))
        : "l"(reinterpret_cast<unsigned long long&>(a)),
          "l"(reinterpret_cast<unsigned long long&>(b)),
          "l"(reinterpret_cast<unsigned long long&>(c)));
    return d;
}

// Transpose-load 128 rows x 64 f from global (row stride ROWSTR) into f-major
// smem tile [64][132].  Mapping keeps global 64B-per-row coalescing and limits
// smem store conflicts to 2-way (pitch 132: 4*132 % 32 == 16).
__device__ __forceinline__ void load_T128(float* __restrict__ dst,
                                          const float* __restrict__ src, int tid) {
#pragma unroll
    for (int it = 0; it < 8; it++) {
        int v  = tid + it * 256;
        int j  = (v >> 2) & 127;
        int f4 = (v & 3) | ((v >> 9) << 2);
        float4 x = *reinterpret_cast<const float4*>(src + j * ROWSTR + (f4 << 2));
        int f = f4 << 2;
        dst[(f + 0) * 132 + j] = x.x;
        dst[(f + 1) * 132 + j] = x.y;
        dst[(f + 2) * 132 + j] = x.z;
        dst[(f + 3) * 132 + j] = x.w;
    }
}

// ---------------------------------------------------------------------------
// Kernel 1: G = E @ E^T   (512x512, K=64) — tiny, 64 CTAs
// ---------------------------------------------------------------------------
__global__ void g_kernel(const float* __restrict__ E) {
    __shared__ float sEi[64][65];
    __shared__ float sEj[64][65];
    int bi = blockIdx.x, bj = blockIdx.y;
    int tid = threadIdx.x;
#pragma unroll
    for (int it = 0; it < 4; it++) {
        int v = tid + it * 256;
        int r = v >> 4, f = (v & 15) << 2;
        float4 a = *reinterpret_cast<const float4*>(E + (bi * 64 + r) * 64 + f);
        sEi[r][f + 0] = a.x; sEi[r][f + 1] = a.y; sEi[r][f + 2] = a.z; sEi[r][f + 3] = a.w;
        float4 c = *reinterpret_cast<const float4*>(E + (bj * 64 + r) * 64 + f);
        sEj[r][f + 0] = c.x; sEj[r][f + 1] = c.y; sEj[r][f + 2] = c.z; sEj[r][f + 3] = c.w;
    }
    __syncthreads();
    int tr = tid >> 4, tc = tid & 15;
    float acc[4][4] = {};
#pragma unroll 8
    for (int f = 0; f < 64; f++) {
        float a[4], b[4];
#pragma unroll
        for (int k = 0; k < 4; k++) { a[k] = sEi[tr * 4 + k][f]; b[k] = sEj[tc * 4 + k][f]; }
#pragma unroll
        for (int i = 0; i < 4; i++)
#pragma unroll
            for (int j = 0; j < 4; j++) acc[i][j] += a[i] * b[j];
    }
#pragma unroll
    for (int i = 0; i < 4; i++)
#pragma unroll
        for (int j = 0; j < 4; j++)
            g_G[(bi * 64 + tr * 4 + i) * NPTS + bj * 64 + tc * 4 + j] = acc[i][j];
}

// ---------------------------------------------------------------------------
// Kernel 2: VW[s][n][0:64] = x@W1^T, [64:128] = u@W1^T   (batched 512x64 @ 64x64)
// grid (384, 4): slice s, 128-row block.  256 thr: 32x8, 4 rows x 8 cols x {x,u}.
// ---------------------------------------------------------------------------
__global__ __launch_bounds__(256, 2)
void vw_kernel(const float* __restrict__ ori, const float* __restrict__ unc,
               const float* __restrict__ W1) {
    extern __shared__ float sm[];
    float* sW = sm;                 // [64][68]  f-major (W1^T)
    float* sX = sm + 4352;          // [64][132] f-major
    float* sU = sm + 4352 + 8448;
    int s = blockIdx.x, nb = blockIdx.y;
    int b = s / TDIM, t = s % TDIM;
    int tid = threadIdx.x;
#pragma unroll
    for (int it = 0; it < 4; it++) {
        int v  = tid + it * 256;
        int o  = (v >> 2) & 63;
        int f4 = (v & 3) | ((v >> 8) << 2);
        float4 w = *reinterpret_cast<const float4*>(W1 + o * 64 + (f4 << 2));
        int f = f4 << 2;
        sW[(f + 0) * 68 + o] = w.x; sW[(f + 1) * 68 + o] = w.y;
        sW[(f + 2) * 68 + o] = w.z; sW[(f + 3) * 68 + o] = w.w;
    }
    const float* xb = ori + ((b * NPTS + nb * 128) * TDIM + t) * FDIM;
    const float* ub = unc + ((b * NPTS + nb * 128) * TDIM + t) * FDIM;
    load_T128(sX, xb, tid);
    load_T128(sU, ub, tid);
    __syncthreads();
    int tr = tid >> 3, tc = tid & 7;          // rows tr*4.., cols tc*8..
    float2 ax[2][8] = {}, au[2][8] = {};
#pragma unroll 4
    for (int f = 0; f < 64; f++) {
        float4 xv = *reinterpret_cast<const float4*>(sX + f * 132 + tr * 4);
        float4 uv = *reinterpret_cast<const float4*>(sU + f * 132 + tr * 4);
        float4 w0 = *reinterpret_cast<const float4*>(sW + f * 68 + tc * 8);
        float4 w1 = *reinterpret_cast<const float4*>(sW + f * 68 + tc * 8 + 4);
        float2 xp[2] = { {xv.x, xv.y}, {xv.z, xv.w} };
        float2 up[2] = { {uv.x, uv.y}, {uv.z, uv.w} };
        float ws[8] = { w0.x, w0.y, w0.z, w0.w, w1.x, w1.y, w1.z, w1.w };
#pragma unroll
        for (int c = 0; c < 8; c++) {
            float2 wd = make_float2(ws[c], ws[c]);
            ax[0][c] = ffma2(xp[0], wd, ax[0][c]);
            ax[1][c] = ffma2(xp[1], wd, ax[1][c]);
            au[0][c] = ffma2(up[0], wd, au[0][c]);
            au[1][c] = ffma2(up[1], wd, au[1][c]);
        }
    }
    int n0 = nb * 128 + tr * 4;
#pragma unroll
    for (int p = 0; p < 2; p++) {
        float* d0 = g_VW + (s * NPTS + n0 + 2 * p) * 128 + tc * 8;   // even row
        float* d1 = d0 + 128;                                        // odd row
        *reinterpret_cast<float4*>(d0)      = make_float4(ax[p][0].x, ax[p][1].x, ax[p][2].x, ax[p][3].x);
        *reinterpret_cast<float4*>(d0 + 4)  = make_float4(ax[p][4].x, ax[p][5].x, ax[p][6].x, ax[p][7].x);
        *reinterpret_cast<float4*>(d0 + 64) = make_float4(au[p][0].x, au[p][1].x, au[p][2].x, au[p][3].x);
        *reinterpret_cast<float4*>(d0 + 68) = make_float4(au[p][4].x, au[p][5].x, au[p][6].x, au[p][7].x);
        *reinterpret_cast<float4*>(d1)      = make_float4(ax[p][0].y, ax[p][1].y, ax[p][2].y, ax[p][3].y);
        *reinterpret_cast<float4*>(d1 + 4)  = make_float4(ax[p][4].y, ax[p][5].y, ax[p][6].y, ax[p][7].y);
        *reinterpret_cast<float4*>(d1 + 64) = make_float4(au[p][0].y, au[p][1].y, au[p][2].y, au[p][3].y);
        *reinterpret_cast<float4*>(d1 + 68) = make_float4(au[p][4].y, au[p][5].y, au[p][6].y, au[p][7].y);
    }
}

// ---------------------------------------------------------------------------
// Kernel 3: fused flash-attention-style pass.
// grid (4, 384): 128-row block ib, slice s.  256 thr: tr=tid>>4, tc=tid&15,
// 8x8 register tile.  4 iterations over 128-col K/V tiles; online softmax.
// ---------------------------------------------------------------------------
__global__ __launch_bounds__(256, 1)
void fa_kernel(const float* __restrict__ ori, float* __restrict__ out) {
    extern __shared__ float sm[];
    float* sQ = sm;            // [64][132] f-major
    float* sK = sm + 8448;     // [64][132] f-major
    float* sV = sm + 16896;    // [128][128]
    float* sP = sm + 33280;    // [128][128] m-major, XOR swizzled (bits 2..4)
    int ib = blockIdx.x, s = blockIdx.y;
    int b = s / TDIM, t = s % TDIM;
    int tid = threadIdx.x;
    const float* xbase = ori + ((b * NPTS) * TDIM + t) * FDIM;   // + n*ROWSTR + f

    load_T128(sQ, xbase + (ib * 128) * ROWSTR, tid);

    int tr = tid >> 4, tc = tid & 15;
    float2 acc[4][8] = {};
    float mrow[8] = {}, lrow[8] = {};   // relu(s) >= 0 => running max init 0 is exact

    for (int kt = 0; kt < 4; kt++) {
        __syncthreads();
        load_T128(sK, xbase + (kt * 128) * ROWSTR, tid);
        {
            const float* vsrc = g_VW + (s * NPTS + kt * 128) * 128;
#pragma unroll
            for (int it = 0; it < 16; it++) {
                int v = tid + it * 256;
                int m = v >> 5, c4 = (v & 31) << 2;
                *reinterpret_cast<float4*>(sV + m * 128 + c4) =
                    *reinterpret_cast<const float4*>(vsrc + m * 128 + c4);
            }
        }
        __syncthreads();

        // ---- GEMM1: S = Q @ K^T ----
        float2 s2[4][8] = {};
#pragma unroll 4
        for (int f = 0; f < 64; f++) {
            float4 q0 = *reinterpret_cast<const float4*>(sQ + f * 132 + tr * 8);
            float4 q1 = *reinterpret_cast<const float4*>(sQ + f * 132 + tr * 8 + 4);
            float4 k0 = *reinterpret_cast<const float4*>(sK + f * 132 + tc * 8);
            float4 k1 = *reinterpret_cast<const float4*>(sK + f * 132 + tc * 8 + 4);
            float2 qp[4] = { {q0.x,q0.y}, {q0.z,q0.w}, {q1.x,q1.y}, {q1.z,q1.w} };
            float kk[8] = { k0.x,k0.y,k0.z,k0.w, k1.x,k1.y,k1.z,k1.w };
#pragma unroll
            for (int c = 0; c < 8; c++) {
                float2 kd = make_float2(kk[c], kk[c]);
#pragma unroll
                for (int p = 0; p < 4; p++) s2[p][c] = ffma2(qp[p], kd, s2[p][c]);
            }
        }

        // ---- + G, relu ----
        const float* gbase = g_G + (ib * 128 + tr * 8) * NPTS + kt * 128 + tc * 8;
#pragma unroll
        for (int r = 0; r < 8; r++) {
            float4 g0 = *reinterpret_cast<const float4*>(gbase + r * NPTS);
            float4 g1 = *reinterpret_cast<const float4*>(gbase + r * NPTS + 4);
            float gg[8] = { g0.x,g0.y,g0.z,g0.w, g1.x,g1.y,g1.z,g1.w };
            int p = r >> 1;
            if ((r & 1) == 0) {
#pragma unroll
                for (int c = 0; c < 8; c++) s2[p][c].x = fmaxf(s2[p][c].x + gg[c], 0.f);
            } else {
#pragma unroll
                for (int c = 0; c < 8; c++) s2[p][c].y = fmaxf(s2[p][c].y + gg[c], 0.f);
            }
        }

        // ---- online softmax (rows shared by 16 tc lanes; xor-shfl within 16) ----
#pragma unroll
        for (int p = 0; p < 4; p++) {
            float mx = 0.f, my = 0.f;
#pragma unroll
            for (int c = 0; c < 8; c++) { mx = fmaxf(mx, s2[p][c].x); my = fmaxf(my, s2[p][c].y); }
#pragma unroll
            for (int d = 8; d; d >>= 1) {
                mx = fmaxf(mx, __shfl_xor_sync(0xffffffffu, mx, d));
                my = fmaxf(my, __shfl_xor_sync(0xffffffffu, my, d));
            }
            float m0 = fmaxf(mrow[2 * p], mx), m1 = fmaxf(mrow[2 * p + 1], my);
            float a0 = __expf(mrow[2 * p] - m0), a1 = __expf(mrow[2 * p + 1] - m1);
            mrow[2 * p] = m0; mrow[2 * p + 1] = m1;
            float sx = 0.f, sy = 0.f;
#pragma unroll
            for (int c = 0; c < 8; c++) {
                float ex = __expf(s2[p][c].x - m0); s2[p][c].x = ex; sx += ex;
                float ey = __expf(s2[p][c].y - m1); s2[p][c].y = ey; sy += ey;
            }
#pragma unroll
            for (int d = 8; d; d >>= 1) {
                sx += __shfl_xor_sync(0xffffffffu, sx, d);
                sy += __shfl_xor_sync(0xffffffffu, sy, d);
            }
            lrow[2 * p] = lrow[2 * p] * a0 + sx;
            lrow[2 * p + 1] = lrow[2 * p + 1] * a1 + sy;
#pragma unroll
            for (int c = 0; c < 8; c++) { acc[p][c].x *= a0; acc[p][c].y *= a1; }
        }

        // ---- store P (m-major, swizzled: pos(i) = i ^ ((m>>3 & 7)<<2)) ----
        {
            int sw = (tc & 7) << 2;   // (m>>3)&7 == tc&7 for m = tc*8+c
#pragma unroll
            for (int c = 0; c < 8; c++) {
                float* pb = sP + (tc * 8 + c) * 128;
                *reinterpret_cast<float4*>(pb + ((tr * 8) ^ sw)) =
                    make_float4(s2[0][c].x, s2[0][c].y, s2[1][c].x, s2[1][c].y);
                *reinterpret_cast<float4*>(pb + ((tr * 8 + 4) ^ sw)) =
                    make_float4(s2[2][c].x, s2[2][c].y, s2[3][c].x, s2[3][c].y);
            }
        }
        __syncthreads();

        // ---- GEMM2: acc += P @ V ----
#pragma unroll 4
        for (int m = 0; m < 128; m++) {
            int sw = ((m >> 3) & 7) << 2;
            const float* pb = sP + m * 128;
            float4 p0 = *reinterpret_cast<const float4*>(pb + ((tr * 8) ^ sw));
            float4 p1 = *reinterpret_cast<const float4*>(pb + ((tr * 8 + 4) ^ sw));
            float4 v0 = *reinterpret_cast<const float4*>(sV + m * 128 + tc * 8);
            float4 v1 = *reinterpret_cast<const float4*>(sV + m * 128 + tc * 8 + 4);
            float2 pp[4] = { {p0.x,p0.y}, {p0.z,p0.w}, {p1.x,p1.y}, {p1.z,p1.w} };
            float vv[8] = { v0.x,v0.y,v0.z,v0.w, v1.x,v1.y,v1.z,v1.w };
#pragma unroll
            for (int c = 0; c < 8; c++) {
                float2 vd = make_float2(vv[c], vv[c]);
#pragma unroll
                for (int p = 0; p < 4; p++) acc[p][c] = ffma2(pp[p], vd, acc[p][c]);
            }
        }
    }

    // ---- epilogue: normalize, relu, scatter to (B,N,T,F) for of / uf ----
    int nbase = ib * 128 + tr * 8;
    int half = (tc >> 3) * OUT_HALF;     // tc<8 -> of, tc>=8 -> uf
    int f0 = (tc & 7) << 3;
#pragma unroll
    for (int p = 0; p < 4; p++) {
        float i0 = 1.f / lrow[2 * p], i1 = 1.f / lrow[2 * p + 1];
        float ox[8], oy[8];
#pragma unroll
        for (int c = 0; c < 8; c++) {
            ox[c] = fmaxf(acc[p][c].x * i0, 0.f);
            oy[c] = fmaxf(acc[p][c].y * i1, 0.f);
        }
        float* d0 = out + half + ((b * NPTS + nbase + 2 * p) * TDIM + t) * FDIM + f0;
        float* d1 = d0 + ROWSTR;   // next n
        *reinterpret_cast<float4*>(d0)     = make_float4(ox[0], ox[1], ox[2], ox[3]);
        *reinterpret_cast<float4*>(d0 + 4) = make_float4(ox[4], ox[5], ox[6], ox[7]);
        *reinterpret_cast<float4*>(d1)     = make_float4(oy[0], oy[1], oy[2], oy[3]);
        *reinterpret_cast<float4*>(d1 + 4) = make_float4(oy[4], oy[5], oy[6], oy[7]);
    }
}

// ---------------------------------------------------------------------------
extern "C" void kernel_launch(void* const* d_in, const int* in_sizes, int n_in,
                              void* d_out, int out_size) {
    const float* ori = (const float*)d_in[0];
    const float* unc = (const float*)d_in[1];
    const float* emb = (const float*)d_in[2];
    const float* W1  = (const float*)d_in[3];
    float* out = (float*)d_out;

    cudaFuncSetAttribute(vw_kernel, cudaFuncAttributeMaxDynamicSharedMemorySize, 84992);
    cudaFuncSetAttribute(fa_kernel, cudaFuncAttributeMaxDynamicSharedMemorySize, 198656);

    g_kernel<<<dim3(8, 8), 256>>>(emb);
    vw_kernel<<<dim3(NSLICE, 4), 256, 84992>>>(ori, unc, W1);
    fa_kernel<<<dim3(4, NSLICE), 256, 198656>>>(ori, out);
}